// round 1
// baseline (speedup 1.0000x reference)
#include <cuda_runtime.h>

#define NN 50000
#define NE 600000
#define EE 650000   // NE + NN self loops
#define NG 32
#define HC 128
#define NH 4
#define OUTD 10

// ---------------- scratch (device global; no allocs allowed) ----------------
// layout (floats):
//  XL 0..6.4M | XR 6.4..12.8M | H 12.8..19.2M | H2 19.2..25.6M
//  ALPHA 25.6..28.2M | AMAX 28.2..28.4M | DEN 28.4..28.6M
//  LOOP 28.6M | CNT 28.65M | POOL 28.70M | GCNT +4096
__device__ float g_buf[28800000];

#define OFF_XL 0
#define OFF_XR 6400000
#define OFF_H  12800000
#define OFF_H2 19200000
#define OFF_AL 25600000
#define OFF_AM 28200000
#define OFF_DN 28400000
#define OFF_LP 28600000
#define OFF_CT 28650000
#define OFF_PL 28700000
#define OFF_GC 28704096

__device__ __forceinline__ void red_add_v4(float* p, float4 v) {
    asm volatile("red.global.add.v4.f32 [%0], {%1,%2,%3,%4};"
                 :: "l"(p), "f"(v.x), "f"(v.y), "f"(v.z), "f"(v.w) : "memory");
}

// ---------------- self-loop attr (fill_value='mean') ----------------
__global__ void k_zero_loop(float* loop, float* cnt) {
    int i = blockIdx.x * blockDim.x + threadIdx.x;
    if (i < NN) { loop[i] = 0.f; cnt[i] = 0.f; }
}
__global__ void k_loop_accum(const int* __restrict__ ei, const float* __restrict__ ew,
                             float* loop, float* cnt) {
    int i = blockIdx.x * blockDim.x + threadIdx.x;
    if (i < NE) {
        int d = ei[NE + i];
        atomicAdd(&cnt[d], 1.f);
        atomicAdd(&loop[d], ew[i]);
    }
}
__global__ void k_loop_final(float* loop, const float* cnt) {
    int i = blockIdx.x * blockDim.x + threadIdx.x;
    if (i < NN) loop[i] = loop[i] / fmaxf(cnt[i], 1.f);
}

// ---------------- fused dual GEMM: outL = X@Wl+bl, outR = X@Wr+br ----------------
// block: 64 rows x 256 out-cols (cols 0..127 -> L, 128..255 -> R), threads (32,8),
// 8x8 register tile per thread, x tile + W k-chunk in shared.
__global__ __launch_bounds__(256) void gemm_dual(
    const float* __restrict__ X,
    const float* __restrict__ Wl, const float* __restrict__ bl,
    const float* __restrict__ Wr, const float* __restrict__ br,
    float* __restrict__ outL, float* __restrict__ outR, int n)
{
    __shared__ float xs[64][128];
    __shared__ float ws[8][256];
    const int t = threadIdx.y * 32 + threadIdx.x;
    const int row0 = blockIdx.x * 64;

    for (int i = t; i < 64 * 32; i += 256) {
        int r = i >> 5, c = (i & 31) * 4;
        float4 v = make_float4(0.f, 0.f, 0.f, 0.f);
        if (row0 + r < n) v = *(const float4*)&X[(size_t)(row0 + r) * HC + c];
        *(float4*)&xs[r][c] = v;
    }

    float acc[8][8];
#pragma unroll
    for (int i = 0; i < 8; i++)
#pragma unroll
        for (int j = 0; j < 8; j++) acc[i][j] = 0.f;

    const int colb = threadIdx.x * 8;
    const int rowb = threadIdx.y * 8;

    for (int k0 = 0; k0 < 128; k0 += 8) {
        __syncthreads();
        for (int i = t; i < 8 * 64; i += 256) {
            int kk = i >> 6, c = (i & 63) * 4;
            float4 v;
            if (c < 128) v = *(const float4*)&Wl[(k0 + kk) * HC + c];
            else         v = *(const float4*)&Wr[(k0 + kk) * HC + c - 128];
            *(float4*)&ws[kk][c] = v;
        }
        __syncthreads();
#pragma unroll
        for (int kk = 0; kk < 8; kk++) {
            float xv[8], wv[8];
#pragma unroll
            for (int i = 0; i < 8; i++) xv[i] = xs[rowb + i][k0 + kk];
#pragma unroll
            for (int j = 0; j < 8; j++) wv[j] = ws[kk][colb + j];
#pragma unroll
            for (int i = 0; i < 8; i++)
#pragma unroll
                for (int j = 0; j < 8; j++) acc[i][j] += xv[i] * wv[j];
        }
    }

    float bv[8];
    const float* bp = (colb < 128) ? (bl + colb) : (br + colb - 128);
#pragma unroll
    for (int j = 0; j < 8; j++) bv[j] = bp[j];
    float* op = (colb < 128) ? (outL + colb) : (outR + colb - 128);
#pragma unroll
    for (int i = 0; i < 8; i++) {
        int row = row0 + rowb + i;
        if (row < n) {
#pragma unroll
            for (int j = 0; j < 8; j += 4) {
                float4 v = make_float4(acc[i][j] + bv[j], acc[i][j + 1] + bv[j + 1],
                                       acc[i][j + 2] + bv[j + 2], acc[i][j + 3] + bv[j + 3]);
                *(float4*)&op[(size_t)row * HC + j] = v;
            }
        }
    }
}

// ---------------- per-layer init: out = bias (broadcast), amax=-inf, den=0 ----------------
__global__ void k_layer_init(const float* __restrict__ bias, float* out,
                             float* amax, float* den) {
    int i = blockIdx.x * blockDim.x + threadIdx.x;
    if (i < NN * HC) out[i] = bias[i & (HC - 1)];
    if (i < NN * NH) { amax[i] = __int_as_float(0xff800000); den[i] = 0.f; }
}

// ---------------- edge pass A: alpha + segment max (warp per edge) ----------------
__global__ __launch_bounds__(256) void k_edge_alpha(
    const float* __restrict__ xl, const float* __restrict__ xr,
    const int* __restrict__ ei, const float* __restrict__ ew,
    const float* __restrict__ loop,
    const float* __restrict__ We, const float* __restrict__ att,
    float* __restrict__ alpha, float* __restrict__ amax)
{
    int gw = (blockIdx.x * 256 + threadIdx.x) >> 5;
    int lane = threadIdx.x & 31;
    if (gw >= EE) return;
    int src, dst; float w;
    if (gw < NE) { src = ei[gw]; dst = ei[NE + gw]; w = ew[gw]; }
    else         { src = dst = gw - NE; w = loop[src]; }

    float4 a  = *(const float4*)&xl[(size_t)src * HC + lane * 4];
    float4 b  = *(const float4*)&xr[(size_t)dst * HC + lane * 4];
    float4 we = *(const float4*)&We[lane * 4];
    float4 at = *(const float4*)&att[lane * 4];

    float m0 = a.x + b.x + w * we.x; m0 = (m0 > 0.f) ? m0 : 0.2f * m0;
    float m1 = a.y + b.y + w * we.y; m1 = (m1 > 0.f) ? m1 : 0.2f * m1;
    float m2 = a.z + b.z + w * we.z; m2 = (m2 > 0.f) ? m2 : 0.2f * m2;
    float m3 = a.w + b.w + w * we.w; m3 = (m3 > 0.f) ? m3 : 0.2f * m3;
    float s = m0 * at.x + m1 * at.y + m2 * at.z + m3 * at.w;
    // reduce over the 8 lanes of this head (C=32 -> 8 lanes/head)
    s += __shfl_xor_sync(0xffffffffu, s, 4);
    s += __shfl_xor_sync(0xffffffffu, s, 2);
    s += __shfl_xor_sync(0xffffffffu, s, 1);
    if ((lane & 7) == 0) {
        int h = lane >> 3;
        alpha[(size_t)gw * NH + h] = s;
        float* p = &amax[(size_t)dst * NH + h];
        if (s >= 0.f) atomicMax((int*)p, __float_as_int(s));
        else atomicMin((unsigned int*)p, (unsigned int)__float_as_int(s));
    }
}

// ---------------- edge pass B: exp + segment denom (thread per edge) ----------------
__global__ void k_edge_softmax(const int* __restrict__ ei,
                               float* __restrict__ alpha,
                               const float* __restrict__ amax,
                               float* __restrict__ den)
{
    int e = blockIdx.x * blockDim.x + threadIdx.x;
    if (e >= EE) return;
    int dst = (e < NE) ? ei[NE + e] : (e - NE);
    float4 al = *(float4*)&alpha[(size_t)e * NH];
    float4 mx = *(const float4*)&amax[(size_t)dst * NH];
    float4 ex = make_float4(expf(al.x - mx.x), expf(al.y - mx.y),
                            expf(al.z - mx.z), expf(al.w - mx.w));
    *(float4*)&alpha[(size_t)e * NH] = ex;
    red_add_v4(&den[(size_t)dst * NH], ex);
}

// ---------------- edge pass C: scatter a * xl[src] into out (warp per edge) ----------------
__global__ __launch_bounds__(256) void k_edge_scatter(
    const float* __restrict__ xl, const int* __restrict__ ei,
    const float* __restrict__ alpha, const float* __restrict__ den,
    float* __restrict__ out)
{
    int gw = (blockIdx.x * 256 + threadIdx.x) >> 5;
    int lane = threadIdx.x & 31;
    if (gw >= EE) return;
    int src, dst;
    if (gw < NE) { src = ei[gw]; dst = ei[NE + gw]; }
    else         { src = dst = gw - NE; }

    float4 ex = *(const float4*)&alpha[(size_t)gw * NH];
    float4 dn = *(const float4*)&den[(size_t)dst * NH];
    float a0 = ex.x / (dn.x + 1e-16f);
    float a1 = ex.y / (dn.y + 1e-16f);
    float a2 = ex.z / (dn.z + 1e-16f);
    float a3 = ex.w / (dn.w + 1e-16f);
    int h = lane >> 3;
    float ah = (h == 0) ? a0 : (h == 1) ? a1 : (h == 2) ? a2 : a3;

    float4 xv = *(const float4*)&xl[(size_t)src * HC + lane * 4];
    float4 v = make_float4(ah * xv.x, ah * xv.y, ah * xv.z, ah * xv.w);
    red_add_v4(&out[(size_t)dst * HC + lane * 4], v);
}

// ---------------- pooling + fc ----------------
__global__ void k_pool_zero(float* pool, float* gcnt) {
    int i = blockIdx.x * blockDim.x + threadIdx.x;
    if (i < NG * HC) pool[i] = 0.f;
    if (i < NG) gcnt[i] = 0.f;
}
__global__ void k_pool_accum(const float* __restrict__ h, const int* __restrict__ batch,
                             float* pool, float* gcnt) {
    int gw = (blockIdx.x * 256 + threadIdx.x) >> 5;
    int lane = threadIdx.x & 31;
    if (gw >= NN) return;
    int b = batch[gw];
    float4 v = *(const float4*)&h[(size_t)gw * HC + lane * 4];
    red_add_v4(&pool[(size_t)b * HC + lane * 4], v);
    if (lane == 0) atomicAdd(&gcnt[b], 1.f);
}
__global__ void k_pool_final(float* pool, const float* gcnt, float* dout, int write_pool) {
    int i = blockIdx.x * blockDim.x + threadIdx.x;
    if (i >= NG * HC) return;
    int g = i >> 7;
    float v = pool[i] / fmaxf(gcnt[g], 1.f);
    pool[i] = v;
    if (write_pool) dout[NG * OUTD + i] = v;
}
__global__ void k_fc(const float* __restrict__ pool, const float* __restrict__ W,
                     const float* __restrict__ b, float* dout) {
    int t = threadIdx.x;
    if (t >= NG * OUTD) return;
    int g = t / OUTD, o = t % OUTD;
    float s = b[o];
#pragma unroll 8
    for (int c = 0; c < HC; c++) s += pool[g * HC + c] * W[c * OUTD + o];
    dout[g * OUTD + o] = s;
}

// ---------------- host driver ----------------
extern "C" void kernel_launch(void* const* d_in, const int* in_sizes, int n_in,
                              void* d_out, int out_size) {
    const float* x    = (const float*)d_in[0];
    const int*   ei   = (const int*)d_in[1];
    const float* ew   = (const float*)d_in[2];
    const int*   batch= (const int*)d_in[3];
    const float* Wl1  = (const float*)d_in[4];
    const float* bl1  = (const float*)d_in[5];
    const float* Wr1  = (const float*)d_in[6];
    const float* br1  = (const float*)d_in[7];
    const float* We1  = (const float*)d_in[8];
    const float* att1 = (const float*)d_in[9];
    const float* bias1= (const float*)d_in[10];
    const float* Wl2  = (const float*)d_in[11];
    const float* bl2  = (const float*)d_in[12];
    const float* Wr2  = (const float*)d_in[13];
    const float* br2  = (const float*)d_in[14];
    const float* We2  = (const float*)d_in[15];
    const float* att2 = (const float*)d_in[16];
    const float* bias2= (const float*)d_in[17];
    const float* fcW  = (const float*)d_in[18];
    const float* fcb  = (const float*)d_in[19];
    float* out = (float*)d_out;

    float* base = nullptr;
    cudaGetSymbolAddress((void**)&base, g_buf);
    float* XL = base + OFF_XL;
    float* XR = base + OFF_XR;
    float* Hb = base + OFF_H;
    float* H2 = base + OFF_H2;
    float* AL = base + OFF_AL;
    float* AM = base + OFF_AM;
    float* DN = base + OFF_DN;
    float* LP = base + OFF_LP;
    float* CT = base + OFF_CT;
    float* PL = base + OFF_PL;
    float* GC = base + OFF_GC;

    // self-loop edge attr (mean of incoming)
    k_zero_loop<<<(NN + 255) / 256, 256>>>(LP, CT);
    k_loop_accum<<<(NE + 255) / 256, 256>>>(ei, ew, LP, CT);
    k_loop_final<<<(NN + 255) / 256, 256>>>(LP, CT);

    dim3 gb((NN + 63) / 64);
    dim3 tb(32, 8);
    const int ginit = (NN * HC + 255) / 256;
    const int gedgeW = (EE * 32 + 255) / 256;
    const int gedgeT = (EE + 255) / 256;

    // layer 1
    gemm_dual<<<gb, tb>>>(x, Wl1, bl1, Wr1, br1, XL, XR, NN);
    k_layer_init<<<ginit, 256>>>(bias1, Hb, AM, DN);
    k_edge_alpha<<<gedgeW, 256>>>(XL, XR, ei, ew, LP, We1, att1, AL, AM);
    k_edge_softmax<<<gedgeT, 256>>>(ei, AL, AM, DN);
    k_edge_scatter<<<gedgeW, 256>>>(XL, ei, AL, DN, Hb);

    // layer 2
    gemm_dual<<<gb, tb>>>(Hb, Wl2, bl2, Wr2, br2, XL, XR, NN);
    k_layer_init<<<ginit, 256>>>(bias2, H2, AM, DN);
    k_edge_alpha<<<gedgeW, 256>>>(XL, XR, ei, ew, LP, We2, att2, AL, AM);
    k_edge_softmax<<<gedgeT, 256>>>(ei, AL, AM, DN);
    k_edge_scatter<<<gedgeW, 256>>>(XL, ei, AL, DN, H2);

    // mean pool per graph + fc
    k_pool_zero<<<(NG * HC + 255) / 256, 256>>>(PL, GC);
    k_pool_accum<<<(NN * 32 + 255) / 256, 256>>>(H2, batch, PL, GC);
    int wp = (out_size >= NG * OUTD + NG * HC) ? 1 : 0;
    k_pool_final<<<(NG * HC + 255) / 256, 256>>>(PL, GC, out, wp);
    k_fc<<<1, NG * OUTD>>>(PL, fcW, fcb, out);
}

// round 2
// speedup vs baseline: 1.6058x; 1.6058x over previous
#include <cuda_runtime.h>

#define NN 50000
#define NE 600000
#define NG 32
#define HC 128
#define NH 4
#define OUTD 10

// ---------------- scratch (device global; no allocs allowed) ----------------
__device__ float g_buf[27200000];

#define OFF_XL   0
#define OFF_XR   6400000
#define OFF_H    12800000
#define OFF_H2   19200000
#define OFF_SSRC 25600000   // int[NE]
#define OFF_SW   26200000   // float[NE]
#define OFF_OFFS 26800000   // int[NN+1]
#define OFF_CUR  26900000   // int[NN]
#define OFF_LP   27000000   // float[NN]
#define OFF_BS   27100000   // int[64] scan block sums
#define OFF_PL   27101000   // float[NG*HC]
#define OFF_GC   27110000   // float[NG]

#define SCAN_BLK 1024
#define SCAN_G   ((NN + SCAN_BLK - 1) / SCAN_BLK)   // 49

__device__ __forceinline__ void red_add_v4(float* p, float4 v) {
    asm volatile("red.global.add.v4.f32 [%0], {%1,%2,%3,%4};"
                 :: "l"(p), "f"(v.x), "f"(v.y), "f"(v.z), "f"(v.w) : "memory");
}

// ---------------- CSR build ----------------
__global__ void k_hist_zero(int* cur, float* lp) {
    int i = blockIdx.x * blockDim.x + threadIdx.x;
    if (i < NN) { cur[i] = 0; lp[i] = 0.f; }
}
__global__ void k_hist(const int* __restrict__ ei, const float* __restrict__ ew,
                       int* cur, float* lp) {
    int e = blockIdx.x * blockDim.x + threadIdx.x;
    if (e < NE) {
        int d = ei[NE + e];
        atomicAdd(&cur[d], 1);
        atomicAdd(&lp[d], ew[e]);
    }
}
// exclusive scan of degrees, 1024 elems / block, 256 threads * 4 elems
__global__ __launch_bounds__(256) void k_scan1(const int* __restrict__ deg,
                                               int* offs, int* bsum) {
    __shared__ int wsum[8];
    int t = threadIdx.x;
    int base = blockIdx.x * SCAN_BLK + t * 4;
    int v0 = 0, v1 = 0, v2 = 0, v3 = 0;
    if (base + 0 < NN) v0 = deg[base + 0];
    if (base + 1 < NN) v1 = deg[base + 1];
    if (base + 2 < NN) v2 = deg[base + 2];
    if (base + 3 < NN) v3 = deg[base + 3];
    int s = v0 + v1 + v2 + v3;
    int lane = t & 31, wid = t >> 5;
    int x = s;
#pragma unroll
    for (int d = 1; d < 32; d <<= 1) {
        int y = __shfl_up_sync(0xffffffffu, x, d);
        if (lane >= d) x += y;
    }
    if (lane == 31) wsum[wid] = x;
    __syncthreads();
    if (t == 0) {
        int a = 0;
#pragma unroll
        for (int i = 0; i < 8; i++) { int tmp = wsum[i]; wsum[i] = a; a += tmp; }
        bsum[blockIdx.x] = a;
    }
    __syncthreads();
    int run = x - s + wsum[wid];   // exclusive prefix within block
    if (base + 0 < NN) offs[base + 0] = run; run += v0;
    if (base + 1 < NN) offs[base + 1] = run; run += v1;
    if (base + 2 < NN) offs[base + 2] = run; run += v2;
    if (base + 3 < NN) offs[base + 3] = run;
}
__global__ void k_scan2(int* bsum) {
    int a = 0;
    for (int b = 0; b < SCAN_G; b++) { int t = bsum[b]; bsum[b] = a; a += t; }
}
__global__ void k_scan3(int* offs, int* cur, const int* __restrict__ bsum) {
    int i = blockIdx.x * blockDim.x + threadIdx.x;
    if (i < NN) {
        int o = offs[i] + bsum[i >> 10];
        offs[i] = o;
        cur[i] = o;
        if (i == 0) offs[NN] = NE;
    }
}
__global__ void k_fill(const int* __restrict__ ei, const float* __restrict__ ew,
                       int* cur, int* ssrc, float* sw) {
    int e = blockIdx.x * blockDim.x + threadIdx.x;
    if (e < NE) {
        int d = ei[NE + e];
        int p = atomicAdd(&cur[d], 1);
        ssrc[p] = ei[e];
        sw[p] = ew[e];
    }
}
__global__ void k_loopdiv(float* lp, const int* __restrict__ offs) {
    int i = blockIdx.x * blockDim.x + threadIdx.x;
    if (i < NN) {
        int deg = offs[i + 1] - offs[i];
        lp[i] = lp[i] / fmaxf((float)deg, 1.f);
    }
}

// ---------------- fused dual GEMM: outL = X@Wl+bl, outR = X@Wr+br ----------------
__global__ __launch_bounds__(256) void gemm_dual(
    const float* __restrict__ X,
    const float* __restrict__ Wl, const float* __restrict__ bl,
    const float* __restrict__ Wr, const float* __restrict__ br,
    float* __restrict__ outL, float* __restrict__ outR, int n)
{
    __shared__ float xs[64][128];
    __shared__ float ws[8][256];
    const int t = threadIdx.y * 32 + threadIdx.x;
    const int row0 = blockIdx.x * 64;

    for (int i = t; i < 64 * 32; i += 256) {
        int r = i >> 5, c = (i & 31) * 4;
        float4 v = make_float4(0.f, 0.f, 0.f, 0.f);
        if (row0 + r < n) v = *(const float4*)&X[(size_t)(row0 + r) * HC + c];
        *(float4*)&xs[r][c] = v;
    }

    float acc[8][8];
#pragma unroll
    for (int i = 0; i < 8; i++)
#pragma unroll
        for (int j = 0; j < 8; j++) acc[i][j] = 0.f;

    const int colb = threadIdx.x * 8;
    const int rowb = threadIdx.y * 8;

    for (int k0 = 0; k0 < 128; k0 += 8) {
        __syncthreads();
        for (int i = t; i < 8 * 64; i += 256) {
            int kk = i >> 6, c = (i & 63) * 4;
            float4 v;
            if (c < 128) v = *(const float4*)&Wl[(k0 + kk) * HC + c];
            else         v = *(const float4*)&Wr[(k0 + kk) * HC + c - 128];
            *(float4*)&ws[kk][c] = v;
        }
        __syncthreads();
#pragma unroll
        for (int kk = 0; kk < 8; kk++) {
            float xv[8], wv[8];
#pragma unroll
            for (int i = 0; i < 8; i++) xv[i] = xs[rowb + i][k0 + kk];
#pragma unroll
            for (int j = 0; j < 8; j++) wv[j] = ws[kk][colb + j];
#pragma unroll
            for (int i = 0; i < 8; i++)
#pragma unroll
                for (int j = 0; j < 8; j++) acc[i][j] += xv[i] * wv[j];
        }
    }

    float bv[8];
    const float* bp = (colb < 128) ? (bl + colb) : (br + colb - 128);
#pragma unroll
    for (int j = 0; j < 8; j++) bv[j] = bp[j];
    float* op = (colb < 128) ? (outL + colb) : (outR + colb - 128);
#pragma unroll
    for (int i = 0; i < 8; i++) {
        int row = row0 + rowb + i;
        if (row < n) {
#pragma unroll
            for (int j = 0; j < 8; j += 4) {
                float4 v = make_float4(acc[i][j] + bv[j], acc[i][j + 1] + bv[j + 1],
                                       acc[i][j + 2] + bv[j + 2], acc[i][j + 3] + bv[j + 3]);
                *(float4*)&op[(size_t)row * HC + j] = v;
            }
        }
    }
}

// ---------------- fused attention layer: warp per dst node over CSR ----------------
// out[d] = (sum_e ex_e * xl[src_e]) / (sum_e ex_e + 1e-16) + bias
// ex_e = exp(alpha_e); alpha ratio identical to max-subtracted softmax.
__global__ __launch_bounds__(256) void k_attn(
    const float* __restrict__ xl, const float* __restrict__ xr,
    const int* __restrict__ offs, const int* __restrict__ ssrc,
    const float* __restrict__ sw, const float* __restrict__ lp,
    const float* __restrict__ We, const float* __restrict__ att,
    const float* __restrict__ bias, float* __restrict__ out)
{
    int gw = (blockIdx.x * 256 + threadIdx.x) >> 5;
    int lane = threadIdx.x & 31;
    if (gw >= NN) return;
    const int c4 = lane * 4;

    float4 xr4 = *(const float4*)&xr[(size_t)gw * HC + c4];
    float4 we4 = *(const float4*)&We[c4];
    float4 at4 = *(const float4*)&att[c4];

    float4 acc = make_float4(0.f, 0.f, 0.f, 0.f);
    float den = 0.f;

    int beg = offs[gw], end = offs[gw + 1];
    for (int e = beg; e <= end; e++) {   // e == end is the self loop
        int src; float w;
        if (e < end) { src = ssrc[e]; w = sw[e]; }
        else         { src = gw;      w = lp[gw]; }
        float4 xl4 = *(const float4*)&xl[(size_t)src * HC + c4];
        float m0 = xl4.x + xr4.x + w * we4.x; m0 = (m0 > 0.f) ? m0 : 0.2f * m0;
        float m1 = xl4.y + xr4.y + w * we4.y; m1 = (m1 > 0.f) ? m1 : 0.2f * m1;
        float m2 = xl4.z + xr4.z + w * we4.z; m2 = (m2 > 0.f) ? m2 : 0.2f * m2;
        float m3 = xl4.w + xr4.w + w * we4.w; m3 = (m3 > 0.f) ? m3 : 0.2f * m3;
        float s = m0 * at4.x + m1 * at4.y + m2 * at4.z + m3 * at4.w;
        // sum over the 8 lanes of this head (butterfly: all lanes get head sum)
        s += __shfl_xor_sync(0xffffffffu, s, 4);
        s += __shfl_xor_sync(0xffffffffu, s, 2);
        s += __shfl_xor_sync(0xffffffffu, s, 1);
        float ex = __expf(s);
        den += ex;
        acc.x += ex * xl4.x;
        acc.y += ex * xl4.y;
        acc.z += ex * xl4.z;
        acc.w += ex * xl4.w;
    }
    float inv = 1.f / (den + 1e-16f);
    float4 o = make_float4(acc.x * inv + bias[c4 + 0],
                           acc.y * inv + bias[c4 + 1],
                           acc.z * inv + bias[c4 + 2],
                           acc.w * inv + bias[c4 + 3]);
    *(float4*)&out[(size_t)gw * HC + c4] = o;
}

// ---------------- pooling + fc ----------------
__global__ void k_pool_zero(float* pool, float* gcnt) {
    int i = blockIdx.x * blockDim.x + threadIdx.x;
    if (i < NG * HC) pool[i] = 0.f;
    if (i < NG) gcnt[i] = 0.f;
}
__global__ void k_pool_accum(const float* __restrict__ h, const int* __restrict__ batch,
                             float* pool, float* gcnt) {
    int gw = (blockIdx.x * 256 + threadIdx.x) >> 5;
    int lane = threadIdx.x & 31;
    if (gw >= NN) return;
    int b = batch[gw];
    float4 v = *(const float4*)&h[(size_t)gw * HC + lane * 4];
    red_add_v4(&pool[(size_t)b * HC + lane * 4], v);
    if (lane == 0) atomicAdd(&gcnt[b], 1.f);
}
__global__ void k_pool_final(float* pool, const float* gcnt, float* dout, int write_pool) {
    int i = blockIdx.x * blockDim.x + threadIdx.x;
    if (i >= NG * HC) return;
    int g = i >> 7;
    float v = pool[i] / fmaxf(gcnt[g], 1.f);
    pool[i] = v;
    if (write_pool) dout[NG * OUTD + i] = v;
}
__global__ void k_fc(const float* __restrict__ pool, const float* __restrict__ W,
                     const float* __restrict__ b, float* dout) {
    int t = threadIdx.x;
    if (t >= NG * OUTD) return;
    int g = t / OUTD, o = t % OUTD;
    float s = b[o];
#pragma unroll 8
    for (int c = 0; c < HC; c++) s += pool[g * HC + c] * W[c * OUTD + o];
    dout[g * OUTD + o] = s;
}

// ---------------- host driver ----------------
extern "C" void kernel_launch(void* const* d_in, const int* in_sizes, int n_in,
                              void* d_out, int out_size) {
    const float* x    = (const float*)d_in[0];
    const int*   ei   = (const int*)d_in[1];
    const float* ew   = (const float*)d_in[2];
    const int*   batch= (const int*)d_in[3];
    const float* Wl1  = (const float*)d_in[4];
    const float* bl1  = (const float*)d_in[5];
    const float* Wr1  = (const float*)d_in[6];
    const float* br1  = (const float*)d_in[7];
    const float* We1  = (const float*)d_in[8];
    const float* att1 = (const float*)d_in[9];
    const float* bias1= (const float*)d_in[10];
    const float* Wl2  = (const float*)d_in[11];
    const float* bl2  = (const float*)d_in[12];
    const float* Wr2  = (const float*)d_in[13];
    const float* br2  = (const float*)d_in[14];
    const float* We2  = (const float*)d_in[15];
    const float* att2 = (const float*)d_in[16];
    const float* bias2= (const float*)d_in[17];
    const float* fcW  = (const float*)d_in[18];
    const float* fcb  = (const float*)d_in[19];
    float* out = (float*)d_out;

    float* base = nullptr;
    cudaGetSymbolAddress((void**)&base, g_buf);
    float* XL   = base + OFF_XL;
    float* XR   = base + OFF_XR;
    float* Hb   = base + OFF_H;
    float* H2   = base + OFF_H2;
    int*   SSRC = (int*)(base + OFF_SSRC);
    float* SW   = base + OFF_SW;
    int*   OFFS = (int*)(base + OFF_OFFS);
    int*   CUR  = (int*)(base + OFF_CUR);
    float* LP   = base + OFF_LP;
    int*   BS   = (int*)(base + OFF_BS);
    float* PL   = base + OFF_PL;
    float* GC   = base + OFF_GC;

    // ---- CSR build (dst-sorted edges) + self-loop attr ----
    k_hist_zero<<<(NN + 255) / 256, 256>>>(CUR, LP);
    k_hist<<<(NE + 255) / 256, 256>>>(ei, ew, CUR, LP);
    k_scan1<<<SCAN_G, 256>>>(CUR, OFFS, BS);
    k_scan2<<<1, 1>>>(BS);
    k_scan3<<<(NN + 255) / 256, 256>>>(OFFS, CUR, BS);
    k_fill<<<(NE + 255) / 256, 256>>>(ei, ew, CUR, SSRC, SW);
    k_loopdiv<<<(NN + 255) / 256, 256>>>(LP, OFFS);

    dim3 gb((NN + 63) / 64);
    dim3 tb(32, 8);
    const int gattn = (NN * 32 + 255) / 256;

    // layer 1
    gemm_dual<<<gb, tb>>>(x, Wl1, bl1, Wr1, br1, XL, XR, NN);
    k_attn<<<gattn, 256>>>(XL, XR, OFFS, SSRC, SW, LP, We1, att1, bias1, Hb);

    // layer 2
    gemm_dual<<<gb, tb>>>(Hb, Wl2, bl2, Wr2, br2, XL, XR, NN);
    k_attn<<<gattn, 256>>>(XL, XR, OFFS, SSRC, SW, LP, We2, att2, bias2, H2);

    // mean pool per graph + fc
    k_pool_zero<<<(NG * HC + 255) / 256, 256>>>(PL, GC);
    k_pool_accum<<<(NN * 32 + 255) / 256, 256>>>(H2, batch, PL, GC);
    int wp = (out_size >= NG * OUTD + NG * HC) ? 1 : 0;
    k_pool_final<<<(NG * HC + 255) / 256, 256>>>(PL, GC, out, wp);
    k_fc<<<1, NG * OUTD>>>(PL, fcW, fcb, out);
}

// round 3
// speedup vs baseline: 2.4799x; 1.5444x over previous
#include <cuda_runtime.h>
#include <cstdint>

#define NN 50000
#define NE 600000
#define NG 32
#define HC 128
#define NH 4
#define OUTD 10

// ---------------- scratch (device global; no allocs allowed) ----------------
__device__ float g_buf[27200000];

#define OFF_XL   0
#define OFF_XR   6400000
#define OFF_H    12800000
#define OFF_H2   19200000
#define OFF_SSRC 25600000   // int[NE]
#define OFF_SW   26200000   // float[NE]
#define OFF_OFFS 26800000   // int[NN+1]
#define OFF_CUR  26900000   // int[NN]
#define OFF_LP   27000000   // float[NN]
#define OFF_BS   27100000   // int[64] scan block sums
#define OFF_PL   27101000   // float[NG*HC]
#define OFF_GC   27110000   // float[NG]

#define SCAN_BLK 1024
#define SCAN_G   ((NN + SCAN_BLK - 1) / SCAN_BLK)   // 49

__device__ __forceinline__ void red_add_v4(float* p, float4 v) {
    asm volatile("red.global.add.v4.f32 [%0], {%1,%2,%3,%4};"
                 :: "l"(p), "f"(v.x), "f"(v.y), "f"(v.z), "f"(v.w) : "memory");
}
__device__ __forceinline__ uint32_t f2tf32(float x) {
    uint32_t r;
    asm("cvt.rna.tf32.f32 %0, %1;" : "=r"(r) : "f"(x));
    return r;
}

// ---------------- CSR build ----------------
__global__ void k_hist_zero(int* cur, float* lp) {
    int i = blockIdx.x * blockDim.x + threadIdx.x;
    if (i < NN) { cur[i] = 0; lp[i] = 0.f; }
}
__global__ void k_hist(const int* __restrict__ ei, const float* __restrict__ ew,
                       int* cur, float* lp) {
    int e = blockIdx.x * blockDim.x + threadIdx.x;
    if (e < NE) {
        int d = ei[NE + e];
        atomicAdd(&cur[d], 1);
        atomicAdd(&lp[d], ew[e]);
    }
}
// exclusive scan of degrees, 1024 elems / block, 256 threads * 4 elems
__global__ __launch_bounds__(256) void k_scan1(const int* __restrict__ deg,
                                               int* offs, int* bsum) {
    __shared__ int wsum[8];
    int t = threadIdx.x;
    int base = blockIdx.x * SCAN_BLK + t * 4;
    int v0 = 0, v1 = 0, v2 = 0, v3 = 0;
    if (base + 0 < NN) v0 = deg[base + 0];
    if (base + 1 < NN) v1 = deg[base + 1];
    if (base + 2 < NN) v2 = deg[base + 2];
    if (base + 3 < NN) v3 = deg[base + 3];
    int s = v0 + v1 + v2 + v3;
    int lane = t & 31, wid = t >> 5;
    int x = s;
#pragma unroll
    for (int d = 1; d < 32; d <<= 1) {
        int y = __shfl_up_sync(0xffffffffu, x, d);
        if (lane >= d) x += y;
    }
    if (lane == 31) wsum[wid] = x;
    __syncthreads();
    if (t == 0) {
        int a = 0;
#pragma unroll
        for (int i = 0; i < 8; i++) { int tmp = wsum[i]; wsum[i] = a; a += tmp; }
        bsum[blockIdx.x] = a;
    }
    __syncthreads();
    int run = x - s + wsum[wid];   // exclusive prefix within block
    if (base + 0 < NN) offs[base + 0] = run; run += v0;
    if (base + 1 < NN) offs[base + 1] = run; run += v1;
    if (base + 2 < NN) offs[base + 2] = run; run += v2;
    if (base + 3 < NN) offs[base + 3] = run;
}
// add bsum prefix (computed block-locally), finalize offs/cur, and do loop-attr divide
__global__ void k_scan3(int* offs, int* cur, const int* __restrict__ bsum, float* lp) {
    __shared__ int spfx;
    int b = blockIdx.x, t = threadIdx.x;
    if (t == 0) {
        int sb = (b * 256) >> 10;   // constant within block (256 | 1024)
        int a = 0;
        for (int j = 0; j < sb; j++) a += bsum[j];
        spfx = a;
    }
    __syncthreads();
    int i = b * 256 + t;
    if (i < NN) {
        int deg = cur[i];           // cur still holds the histogram here
        int o = offs[i] + spfx;
        offs[i] = o;
        cur[i] = o;
        lp[i] = lp[i] / fmaxf((float)deg, 1.f);
        if (i == 0) offs[NN] = NE;
    }
}
__global__ void k_fill(const int* __restrict__ ei, const float* __restrict__ ew,
                       int* cur, int* ssrc, float* sw) {
    int e = blockIdx.x * blockDim.x + threadIdx.x;
    if (e < NE) {
        int d = ei[NE + e];
        int p = atomicAdd(&cur[d], 1);
        ssrc[p] = ei[e];
        sw[p] = ew[e];
    }
}

// ---------------- TF32 tensor-core dual GEMM ----------------
// C[n x 256] = X[n x 128] @ [Wl | Wr][128 x 256] + [bl | br]
// CTA: 128 rows x 256 cols, 512 threads (16 warps, 4x4), warp tile 32x64.
// K chunked by 16. xs stride 20 / ws stride 264 -> conflict-free frag LDS.
#define G_KC  16
#define G_XSS 20
#define G_WSS 264

__device__ __forceinline__ void mma_tf32(float d[4], const uint32_t a[4],
                                         uint32_t b0, uint32_t b1) {
    asm volatile(
        "mma.sync.aligned.m16n8k8.row.col.f32.tf32.tf32.f32 "
        "{%0,%1,%2,%3}, {%4,%5,%6,%7}, {%8,%9}, {%0,%1,%2,%3};"
        : "+f"(d[0]), "+f"(d[1]), "+f"(d[2]), "+f"(d[3])
        : "r"(a[0]), "r"(a[1]), "r"(a[2]), "r"(a[3]), "r"(b0), "r"(b1));
}

__global__ __launch_bounds__(512, 1) void gemm_mma(
    const float* __restrict__ X,
    const float* __restrict__ Wl, const float* __restrict__ bl,
    const float* __restrict__ Wr, const float* __restrict__ br,
    float* __restrict__ outL, float* __restrict__ outR, int n)
{
    __shared__ float xs[128 * G_XSS];   // 10240 B
    __shared__ float ws[G_KC * G_WSS]; // 16896 B
    const int t = threadIdx.x;
    const int row0 = blockIdx.x * 128;
    const int w = t >> 5, lane = t & 31;
    const int gid = lane >> 2, tig = lane & 3;
    const int rb = (w & 3) * 32;       // warp row base
    const int cb = (w >> 2) * 64;      // warp col base

    float acc[2][8][4];
#pragma unroll
    for (int mi = 0; mi < 2; mi++)
#pragma unroll
        for (int ni = 0; ni < 8; ni++)
#pragma unroll
            for (int j = 0; j < 4; j++) acc[mi][ni][j] = 0.f;

    const int xr_ = t >> 2, xc = (t & 3) * 4;        // X loader: 1 float4/thread

    for (int k0 = 0; k0 < 128; k0 += G_KC) {
        // load X chunk [128 x 16] (tf32-rounded)
        {
            float4 v = make_float4(0.f, 0.f, 0.f, 0.f);
            if (row0 + xr_ < n) v = *(const float4*)&X[(size_t)(row0 + xr_) * HC + k0 + xc];
            float* p = &xs[xr_ * G_XSS + xc];
            ((uint32_t*)p)[0] = f2tf32(v.x);
            ((uint32_t*)p)[1] = f2tf32(v.y);
            ((uint32_t*)p)[2] = f2tf32(v.z);
            ((uint32_t*)p)[3] = f2tf32(v.w);
        }
        // load W chunk [16 x 256] (tf32-rounded): 2 float4/thread
#pragma unroll
        for (int rep = 0; rep < 2; rep++) {
            int idx = t + rep * 512;
            int kk = idx >> 6, cq = (idx & 63) * 4;
            float4 v;
            if (cq < 128) v = *(const float4*)&Wl[(k0 + kk) * HC + cq];
            else          v = *(const float4*)&Wr[(k0 + kk) * HC + cq - 128];
            float* p = &ws[kk * G_WSS + cq];
            ((uint32_t*)p)[0] = f2tf32(v.x);
            ((uint32_t*)p)[1] = f2tf32(v.y);
            ((uint32_t*)p)[2] = f2tf32(v.z);
            ((uint32_t*)p)[3] = f2tf32(v.w);
        }
        __syncthreads();

#pragma unroll
        for (int kk = 0; kk < G_KC; kk += 8) {
            uint32_t a[2][4];
#pragma unroll
            for (int mi = 0; mi < 2; mi++) {
                int r = rb + mi * 16 + gid;
                a[mi][0] = __float_as_uint(xs[r * G_XSS + kk + tig]);
                a[mi][1] = __float_as_uint(xs[(r + 8) * G_XSS + kk + tig]);
                a[mi][2] = __float_as_uint(xs[r * G_XSS + kk + tig + 4]);
                a[mi][3] = __float_as_uint(xs[(r + 8) * G_XSS + kk + tig + 4]);
            }
#pragma unroll
            for (int ni = 0; ni < 8; ni++) {
                int c = cb + ni * 8 + gid;
                uint32_t b0 = __float_as_uint(ws[(kk + tig) * G_WSS + c]);
                uint32_t b1 = __float_as_uint(ws[(kk + tig + 4) * G_WSS + c]);
                mma_tf32(acc[0][ni], a[0], b0, b1);
                mma_tf32(acc[1][ni], a[1], b0, b1);
            }
        }
        __syncthreads();
    }

    // epilogue: add bias, write float2 pairs
#pragma unroll
    for (int ni = 0; ni < 8; ni++) {
        int col = cb + ni * 8 + tig * 2;
        const float* bp;
        float* op;
        int c = col;
        if (col < 128) { bp = bl; op = outL; }
        else           { bp = br; op = outR; c = col - 128; }
        float b0v = bp[c], b1v = bp[c + 1];
#pragma unroll
        for (int mi = 0; mi < 2; mi++) {
            int rlo = row0 + rb + mi * 16 + gid;
            int rhi = rlo + 8;
            if (rlo < n) {
                float2 v = make_float2(acc[mi][ni][0] + b0v, acc[mi][ni][1] + b1v);
                *(float2*)&op[(size_t)rlo * HC + c] = v;
            }
            if (rhi < n) {
                float2 v = make_float2(acc[mi][ni][2] + b0v, acc[mi][ni][3] + b1v);
                *(float2*)&op[(size_t)rhi * HC + c] = v;
            }
        }
    }
}

// ---------------- fused attention layer: warp per dst node over CSR ----------------
__global__ __launch_bounds__(256) void k_attn(
    const float* __restrict__ xl, const float* __restrict__ xr,
    const int* __restrict__ offs, const int* __restrict__ ssrc,
    const float* __restrict__ sw, const float* __restrict__ lp,
    const float* __restrict__ We, const float* __restrict__ att,
    const float* __restrict__ bias, float* __restrict__ out)
{
    int gw = (blockIdx.x * 256 + threadIdx.x) >> 5;
    int lane = threadIdx.x & 31;
    if (gw >= NN) return;
    const int c4 = lane * 4;

    float4 xr4 = *(const float4*)&xr[(size_t)gw * HC + c4];
    float4 we4 = *(const float4*)&We[c4];
    float4 at4 = *(const float4*)&att[c4];

    float4 acc = make_float4(0.f, 0.f, 0.f, 0.f);
    float den = 0.f;

    int beg = offs[gw], end = offs[gw + 1];
    for (int e = beg; e <= end; e++) {   // e == end is the self loop
        int src; float w;
        if (e < end) { src = ssrc[e]; w = sw[e]; }
        else         { src = gw;      w = lp[gw]; }
        float4 xl4 = *(const float4*)&xl[(size_t)src * HC + c4];
        float m0 = xl4.x + xr4.x + w * we4.x; m0 = (m0 > 0.f) ? m0 : 0.2f * m0;
        float m1 = xl4.y + xr4.y + w * we4.y; m1 = (m1 > 0.f) ? m1 : 0.2f * m1;
        float m2 = xl4.z + xr4.z + w * we4.z; m2 = (m2 > 0.f) ? m2 : 0.2f * m2;
        float m3 = xl4.w + xr4.w + w * we4.w; m3 = (m3 > 0.f) ? m3 : 0.2f * m3;
        float s = m0 * at4.x + m1 * at4.y + m2 * at4.z + m3 * at4.w;
        s += __shfl_xor_sync(0xffffffffu, s, 4);
        s += __shfl_xor_sync(0xffffffffu, s, 2);
        s += __shfl_xor_sync(0xffffffffu, s, 1);
        float ex = __expf(s);
        den += ex;
        acc.x += ex * xl4.x;
        acc.y += ex * xl4.y;
        acc.z += ex * xl4.z;
        acc.w += ex * xl4.w;
    }
    float inv = 1.f / (den + 1e-16f);
    float4 o = make_float4(acc.x * inv + bias[c4 + 0],
                           acc.y * inv + bias[c4 + 1],
                           acc.z * inv + bias[c4 + 2],
                           acc.w * inv + bias[c4 + 3]);
    *(float4*)&out[(size_t)gw * HC + c4] = o;
}

// ---------------- pooling + fc ----------------
__global__ void k_pool_zero(float* pool, float* gcnt) {
    int i = blockIdx.x * blockDim.x + threadIdx.x;
    if (i < NG * HC) pool[i] = 0.f;
    if (i < NG) gcnt[i] = 0.f;
}
__global__ void k_pool_accum(const float* __restrict__ h, const int* __restrict__ batch,
                             float* pool, float* gcnt) {
    int gw = (blockIdx.x * 256 + threadIdx.x) >> 5;
    int lane = threadIdx.x & 31;
    if (gw >= NN) return;
    int b = batch[gw];
    float4 v = *(const float4*)&h[(size_t)gw * HC + lane * 4];
    red_add_v4(&pool[(size_t)b * HC + lane * 4], v);
    if (lane == 0) atomicAdd(&gcnt[b], 1.f);
}
// single block: finalize pooled means, write pooled output, then FC
__global__ __launch_bounds__(512) void k_tail(
    const float* __restrict__ pool, const float* __restrict__ gcnt,
    const float* __restrict__ W, const float* __restrict__ b,
    float* dout, int write_pool)
{
    __shared__ float pl[NG * HC];
    int t = threadIdx.x;
    for (int i = t; i < NG * HC; i += 512) {
        int g = i >> 7;
        float v = pool[i] / fmaxf(gcnt[g], 1.f);
        pl[i] = v;
        if (write_pool) dout[NG * OUTD + i] = v;
    }
    __syncthreads();
    if (t < NG * OUTD) {
        int g = t / OUTD, o = t % OUTD;
        float s = b[o];
#pragma unroll 8
        for (int c = 0; c < HC; c++) s += pl[g * HC + c] * W[c * OUTD + o];
        dout[g * OUTD + o] = s;
    }
}

// ---------------- host driver ----------------
extern "C" void kernel_launch(void* const* d_in, const int* in_sizes, int n_in,
                              void* d_out, int out_size) {
    const float* x    = (const float*)d_in[0];
    const int*   ei   = (const int*)d_in[1];
    const float* ew   = (const float*)d_in[2];
    const int*   batch= (const int*)d_in[3];
    const float* Wl1  = (const float*)d_in[4];
    const float* bl1  = (const float*)d_in[5];
    const float* Wr1  = (const float*)d_in[6];
    const float* br1  = (const float*)d_in[7];
    const float* We1  = (const float*)d_in[8];
    const float* att1 = (const float*)d_in[9];
    const float* bias1= (const float*)d_in[10];
    const float* Wl2  = (const float*)d_in[11];
    const float* bl2  = (const float*)d_in[12];
    const float* Wr2  = (const float*)d_in[13];
    const float* br2  = (const float*)d_in[14];
    const float* We2  = (const float*)d_in[15];
    const float* att2 = (const float*)d_in[16];
    const float* bias2= (const float*)d_in[17];
    const float* fcW  = (const float*)d_in[18];
    const float* fcb  = (const float*)d_in[19];
    float* out = (float*)d_out;

    float* base = nullptr;
    cudaGetSymbolAddress((void**)&base, g_buf);
    float* XL   = base + OFF_XL;
    float* XR   = base + OFF_XR;
    float* Hb   = base + OFF_H;
    float* H2   = base + OFF_H2;
    int*   SSRC = (int*)(base + OFF_SSRC);
    float* SW   = base + OFF_SW;
    int*   OFFS = (int*)(base + OFF_OFFS);
    int*   CUR  = (int*)(base + OFF_CUR);
    float* LP   = base + OFF_LP;
    int*   BS   = (int*)(base + OFF_BS);
    float* PL   = base + OFF_PL;
    float* GC   = base + OFF_GC;

    // ---- CSR build (dst-sorted edges) + self-loop attr ----
    k_hist_zero<<<(NN + 255) / 256, 256>>>(CUR, LP);
    k_hist<<<(NE + 255) / 256, 256>>>(ei, ew, CUR, LP);
    k_scan1<<<SCAN_G, 256>>>(CUR, OFFS, BS);
    k_scan3<<<(NN + 255) / 256, 256>>>(OFFS, CUR, BS, LP);
    k_fill<<<(NE + 255) / 256, 256>>>(ei, ew, CUR, SSRC, SW);

    const int ggemm = (NN + 127) / 128;
    const int gattn = (NN * 32 + 255) / 256;

    // layer 1
    gemm_mma<<<ggemm, 512>>>(x, Wl1, bl1, Wr1, br1, XL, XR, NN);
    k_attn<<<gattn, 256>>>(XL, XR, OFFS, SSRC, SW, LP, We1, att1, bias1, Hb);

    // layer 2
    gemm_mma<<<ggemm, 512>>>(Hb, Wl2, bl2, Wr2, br2, XL, XR, NN);
    k_attn<<<gattn, 256>>>(XL, XR, OFFS, SSRC, SW, LP, We2, att2, bias2, H2);

    // mean pool per graph + fc
    k_pool_zero<<<(NG * HC + 255) / 256, 256>>>(PL, GC);
    k_pool_accum<<<(NN * 32 + 255) / 256, 256>>>(H2, batch, PL, GC);
    int wp = (out_size >= NG * OUTD + NG * HC) ? 1 : 0;
    k_tail<<<1, 512>>>(PL, GC, fcW, fcb, out, wp);
}

// round 5
// speedup vs baseline: 2.5886x; 1.0438x over previous
#include <cuda_runtime.h>
#include <cstdint>

#define NN 50000
#define NE 600000
#define NG 32
#define HC 128
#define NH 4
#define OUTD 10

// ---------------- scratch (device global; no allocs allowed) ----------------
__device__ float g_buf[27200000];

#define OFF_XL   0
#define OFF_XR   6400000
#define OFF_H    12800000
#define OFF_H2   19200000
#define OFF_SSRC 25600000   // int[NE]
#define OFF_SW   26200000   // float[NE]
#define OFF_OFFS 26800000   // int[NN+1]
#define OFF_CUR  26900000   // int[NN]
#define OFF_LP   27000000   // float[NN]
#define OFF_BS   27100000   // int[64] scan block sums
#define OFF_PL   27101000   // float[NG*HC]
#define OFF_GC   27110000   // float[NG]

#define SCAN_BLK 1024
#define SCAN_G   ((NN + SCAN_BLK - 1) / SCAN_BLK)   // 49

__device__ __forceinline__ void red_add_v4(float* p, float4 v) {
    asm volatile("red.global.add.v4.f32 [%0], {%1,%2,%3,%4};"
                 :: "l"(p), "f"(v.x), "f"(v.y), "f"(v.z), "f"(v.w) : "memory");
}
__device__ __forceinline__ uint32_t f2tf32(float x) {
    uint32_t r;
    asm("cvt.rna.tf32.f32 %0, %1;" : "=r"(r) : "f"(x));
    return r;
}

// ---------------- CSR build ----------------
__global__ void k_hist_zero(int* cur, float* lp, float* pool, float* gcnt) {
    int i = blockIdx.x * blockDim.x + threadIdx.x;
    if (i < NN) { cur[i] = 0; lp[i] = 0.f; }
    if (i < NG * HC) pool[i] = 0.f;
    if (i < NG) gcnt[i] = 0.f;
}
__global__ void k_hist(const int* __restrict__ ei, const float* __restrict__ ew,
                       int* cur, float* lp) {
    int e = blockIdx.x * blockDim.x + threadIdx.x;
    if (e < NE) {
        int d = ei[NE + e];
        atomicAdd(&cur[d], 1);
        atomicAdd(&lp[d], ew[e]);
    }
}
// exclusive scan of degrees, 1024 elems / block, 256 threads * 4 elems
__global__ __launch_bounds__(256) void k_scan1(const int* __restrict__ deg,
                                               int* offs, int* bsum) {
    __shared__ int wsum[8];
    int t = threadIdx.x;
    int base = blockIdx.x * SCAN_BLK + t * 4;
    int v0 = 0, v1 = 0, v2 = 0, v3 = 0;
    if (base + 0 < NN) v0 = deg[base + 0];
    if (base + 1 < NN) v1 = deg[base + 1];
    if (base + 2 < NN) v2 = deg[base + 2];
    if (base + 3 < NN) v3 = deg[base + 3];
    int s = v0 + v1 + v2 + v3;
    int lane = t & 31, wid = t >> 5;
    int x = s;
#pragma unroll
    for (int d = 1; d < 32; d <<= 1) {
        int y = __shfl_up_sync(0xffffffffu, x, d);
        if (lane >= d) x += y;
    }
    if (lane == 31) wsum[wid] = x;
    __syncthreads();
    if (t == 0) {
        int a = 0;
#pragma unroll
        for (int i = 0; i < 8; i++) { int tmp = wsum[i]; wsum[i] = a; a += tmp; }
        bsum[blockIdx.x] = a;
    }
    __syncthreads();
    int run = x - s + wsum[wid];   // exclusive prefix within block
    if (base + 0 < NN) offs[base + 0] = run; run += v0;
    if (base + 1 < NN) offs[base + 1] = run; run += v1;
    if (base + 2 < NN) offs[base + 2] = run; run += v2;
    if (base + 3 < NN) offs[base + 3] = run;
}
// add bsum prefix (computed block-locally), finalize offs/cur, and do loop-attr divide
__global__ void k_scan3(int* offs, int* cur, const int* __restrict__ bsum, float* lp) {
    __shared__ int spfx;
    int b = blockIdx.x, t = threadIdx.x;
    if (t == 0) {
        int sb = (b * 256) >> 10;   // constant within block (256 | 1024)
        int a = 0;
        for (int j = 0; j < sb; j++) a += bsum[j];
        spfx = a;
    }
    __syncthreads();
    int i = b * 256 + t;
    if (i < NN) {
        int deg = cur[i];           // cur still holds the histogram here
        int o = offs[i] + spfx;
        offs[i] = o;
        cur[i] = o;
        lp[i] = lp[i] / fmaxf((float)deg, 1.f);
        if (i == 0) offs[NN] = NE;
    }
}
__global__ void k_fill(const int* __restrict__ ei, const float* __restrict__ ew,
                       int* cur, int* ssrc, float* sw) {
    int e = blockIdx.x * blockDim.x + threadIdx.x;
    if (e < NE) {
        int d = ei[NE + e];
        int p = atomicAdd(&cur[d], 1);
        ssrc[p] = ei[e];
        sw[p] = ew[e];
    }
}

// ---------------- TF32 tensor-core dual GEMM (double-buffered) ----------------
// C[n x 256] = X[n x 128] @ [Wl | Wr][128 x 256] + [bl | br]
// CTA: 128 rows x 256 cols, 512 threads (16 warps, 4x4), warp tile 32x64.
// K chunked by 16, 2-stage smem pipeline: LDG next chunk -> mma current -> STS next.
#define G_KC   16
#define G_XSS  20
#define G_WSS  264
#define G_XSZ  (128 * G_XSS)     // 2560 floats
#define G_WSZ  (G_KC * G_WSS)    // 4224 floats
#define G_SMEM ((2 * G_XSZ + 2 * G_WSZ) * 4)   // 54272 bytes

__device__ __forceinline__ void mma_tf32(float d[4], const uint32_t a[4],
                                         uint32_t b0, uint32_t b1) {
    asm volatile(
        "mma.sync.aligned.m16n8k8.row.col.f32.tf32.tf32.f32 "
        "{%0,%1,%2,%3}, {%4,%5,%6,%7}, {%8,%9}, {%0,%1,%2,%3};"
        : "+f"(d[0]), "+f"(d[1]), "+f"(d[2]), "+f"(d[3])
        : "r"(a[0]), "r"(a[1]), "r"(a[2]), "r"(a[3]), "r"(b0), "r"(b1));
}

__global__ __launch_bounds__(512, 1) void gemm_mma(
    const float* __restrict__ X,
    const float* __restrict__ Wl, const float* __restrict__ bl,
    const float* __restrict__ Wr, const float* __restrict__ br,
    float* __restrict__ outL, float* __restrict__ outR, int n)
{
    extern __shared__ float sm[];
    float* xsb[2] = { sm, sm + G_XSZ };
    float* wsb[2] = { sm + 2 * G_XSZ, sm + 2 * G_XSZ + G_WSZ };

    const int t = threadIdx.x;
    const int row0 = blockIdx.x * 128;
    const int w = t >> 5, lane = t & 31;
    const int gid = lane >> 2, tig = lane & 3;
    const int rb = (w & 3) * 32;       // warp row base
    const int cb = (w >> 2) * 64;      // warp col base

    float acc[2][8][4];
#pragma unroll
    for (int mi = 0; mi < 2; mi++)
#pragma unroll
        for (int ni = 0; ni < 8; ni++)
#pragma unroll
            for (int j = 0; j < 4; j++) acc[mi][ni][j] = 0.f;

    // loader geometry
    const int xr_ = t >> 2, xc = (t & 3) * 4;   // X: one float4/thread
    const int wk = t >> 6, wc = (t & 63) * 4;   // W: rows wk and wk+8, col wc
    const bool xok = (row0 + xr_ < n);
    const float* wsrc = (wc < 128) ? (Wl + wc) : (Wr + wc - 128);

    float4 xv, wv0, wv1;
    auto ldg_chunk = [&](int k0) {
        xv = xok ? *(const float4*)&X[(size_t)(row0 + xr_) * HC + k0 + xc]
                 : make_float4(0.f, 0.f, 0.f, 0.f);
        wv0 = *(const float4*)&wsrc[(k0 + wk) * HC];
        wv1 = *(const float4*)&wsrc[(k0 + wk + 8) * HC];
    };
    auto sts_chunk = [&](int b) {
        float* px = &xsb[b][xr_ * G_XSS + xc];
        ((uint32_t*)px)[0] = f2tf32(xv.x);
        ((uint32_t*)px)[1] = f2tf32(xv.y);
        ((uint32_t*)px)[2] = f2tf32(xv.z);
        ((uint32_t*)px)[3] = f2tf32(xv.w);
        float* p0 = &wsb[b][wk * G_WSS + wc];
        ((uint32_t*)p0)[0] = f2tf32(wv0.x);
        ((uint32_t*)p0)[1] = f2tf32(wv0.y);
        ((uint32_t*)p0)[2] = f2tf32(wv0.z);
        ((uint32_t*)p0)[3] = f2tf32(wv0.w);
        float* p1 = &wsb[b][(wk + 8) * G_WSS + wc];
        ((uint32_t*)p1)[0] = f2tf32(wv1.x);
        ((uint32_t*)p1)[1] = f2tf32(wv1.y);
        ((uint32_t*)p1)[2] = f2tf32(wv1.z);
        ((uint32_t*)p1)[3] = f2tf32(wv1.w);
    };
    auto compute = [&](int b) {
        const float* xs = xsb[b];
        const float* ws = wsb[b];
#pragma unroll
        for (int kk = 0; kk < G_KC; kk += 8) {
            uint32_t a[2][4];
#pragma unroll
            for (int mi = 0; mi < 2; mi++) {
                int r = rb + mi * 16 + gid;
                a[mi][0] = __float_as_uint(xs[r * G_XSS + kk + tig]);
                a[mi][1] = __float_as_uint(xs[(r + 8) * G_XSS + kk + tig]);
                a[mi][2] = __float_as_uint(xs[r * G_XSS + kk + tig + 4]);
                a[mi][3] = __float_as_uint(xs[(r + 8) * G_XSS + kk + tig + 4]);
            }
#pragma unroll
            for (int ni = 0; ni < 8; ni++) {
                int c = cb + ni * 8 + gid;
                uint32_t b0 = __float_as_uint(ws[(kk + tig) * G_WSS + c]);
                uint32_t b1 = __float_as_uint(ws[(kk + tig + 4) * G_WSS + c]);
                mma_tf32(acc[0][ni], a[0], b0, b1);
                mma_tf32(acc[1][ni], a[1], b0, b1);
            }
        }
    };

    ldg_chunk(0);
    sts_chunk(0);
    __syncthreads();
#pragma unroll
    for (int c = 0; c < 8; c++) {
        if (c < 7) ldg_chunk((c + 1) * G_KC);
        compute(c & 1);
        if (c < 7) sts_chunk((c + 1) & 1);
        __syncthreads();
    }

    // epilogue: add bias, write float2 pairs
#pragma unroll
    for (int ni = 0; ni < 8; ni++) {
        int col = cb + ni * 8 + tig * 2;
        const float* bp;
        float* op;
        int c = col;
        if (col < 128) { bp = bl; op = outL; }
        else           { bp = br; op = outR; c = col - 128; }
        float b0v = bp[c], b1v = bp[c + 1];
#pragma unroll
        for (int mi = 0; mi < 2; mi++) {
            int rlo = row0 + rb + mi * 16 + gid;
            int rhi = rlo + 8;
            if (rlo < n) {
                float2 v = make_float2(acc[mi][ni][0] + b0v, acc[mi][ni][1] + b1v);
                *(float2*)&op[(size_t)rlo * HC + c] = v;
            }
            if (rhi < n) {
                float2 v = make_float2(acc[mi][ni][2] + b0v, acc[mi][ni][3] + b1v);
                *(float2*)&op[(size_t)rhi * HC + c] = v;
            }
        }
    }
}

// ---------------- fused attention layer: warp per dst node over CSR ----------------
// software-pipelined: prefetch next edge's xl row before reducing current edge
__global__ __launch_bounds__(256) void k_attn(
    const float* __restrict__ xl, const float* __restrict__ xr,
    const int* __restrict__ offs, const int* __restrict__ ssrc,
    const float* __restrict__ sw, const float* __restrict__ lp,
    const float* __restrict__ We, const float* __restrict__ att,
    const float* __restrict__ bias, float* __restrict__ out)
{
    int gw = (blockIdx.x * 256 + threadIdx.x) >> 5;
    int lane = threadIdx.x & 31;
    if (gw >= NN) return;
    const int c4 = lane * 4;

    float4 xr4 = *(const float4*)&xr[(size_t)gw * HC + c4];
    float4 we4 = *(const float4*)&We[c4];
    float4 at4 = *(const float4*)&att[c4];

    float4 acc = make_float4(0.f, 0.f, 0.f, 0.f);
    float den = 0.f;

    int beg = offs[gw], end = offs[gw + 1];
    // prime edge (e==end is the self loop)
    int src0; float w0;
    if (beg < end) { src0 = ssrc[beg]; w0 = sw[beg]; }
    else           { src0 = gw;        w0 = lp[gw]; }
    float4 x0 = *(const float4*)&xl[(size_t)src0 * HC + c4];

    for (int e = beg; e <= end; e++) {
        float w1 = 0.f; float4 x1;
        if (e < end) {
            int src1;
            if (e + 1 < end) { src1 = ssrc[e + 1]; w1 = sw[e + 1]; }
            else             { src1 = gw;          w1 = lp[gw]; }
            x1 = *(const float4*)&xl[(size_t)src1 * HC + c4];
        }
        float m0 = x0.x + xr4.x + w0 * we4.x; m0 = fmaxf(m0, 0.2f * m0);
        float m1 = x0.y + xr4.y + w0 * we4.y; m1 = fmaxf(m1, 0.2f * m1);
        float m2 = x0.z + xr4.z + w0 * we4.z; m2 = fmaxf(m2, 0.2f * m2);
        float m3 = x0.w + xr4.w + w0 * we4.w; m3 = fmaxf(m3, 0.2f * m3);
        float s = m0 * at4.x + m1 * at4.y + m2 * at4.z + m3 * at4.w;
        s += __shfl_xor_sync(0xffffffffu, s, 4);
        s += __shfl_xor_sync(0xffffffffu, s, 2);
        s += __shfl_xor_sync(0xffffffffu, s, 1);
        float ex = __expf(s);
        den += ex;
        acc.x += ex * x0.x;
        acc.y += ex * x0.y;
        acc.z += ex * x0.z;
        acc.w += ex * x0.w;
        if (e < end) { x0 = x1; w0 = w1; }
    }
    float inv = 1.f / (den + 1e-16f);
    float4 o = make_float4(acc.x * inv + bias[c4 + 0],
                           acc.y * inv + bias[c4 + 1],
                           acc.z * inv + bias[c4 + 2],
                           acc.w * inv + bias[c4 + 3]);
    *(float4*)&out[(size_t)gw * HC + c4] = o;
}

// ---------------- pooling + fc ----------------
__global__ void k_pool_accum(const float* __restrict__ h, const int* __restrict__ batch,
                             float* pool, float* gcnt) {
    int gw = (blockIdx.x * 256 + threadIdx.x) >> 5;
    int lane = threadIdx.x & 31;
    if (gw >= NN) return;
    int b = batch[gw];
    float4 v = *(const float4*)&h[(size_t)gw * HC + lane * 4];
    red_add_v4(&pool[(size_t)b * HC + lane * 4], v);
    if (lane == 0) atomicAdd(&gcnt[b], 1.f);
}
// single block: finalize pooled means, write pooled output, then FC
__global__ __launch_bounds__(512) void k_tail(
    const float* __restrict__ pool, const float* __restrict__ gcnt,
    const float* __restrict__ W, const float* __restrict__ b,
    float* dout, int write_pool)
{
    __shared__ float pl[NG * HC];
    int t = threadIdx.x;
    for (int i = t; i < NG * HC; i += 512) {
        int g = i >> 7;
        float v = pool[i] / fmaxf(gcnt[g], 1.f);
        pl[i] = v;
        if (write_pool) dout[NG * OUTD + i] = v;
    }
    __syncthreads();
    if (t < NG * OUTD) {
        int g = t / OUTD, o = t % OUTD;
        float s = b[o];
#pragma unroll 8
        for (int c = 0; c < HC; c++) s += pl[g * HC + c] * W[c * OUTD + o];
        dout[g * OUTD + o] = s;
    }
}

// ---------------- host driver ----------------
extern "C" void kernel_launch(void* const* d_in, const int* in_sizes, int n_in,
                              void* d_out, int out_size) {
    const float* x    = (const float*)d_in[0];
    const int*   ei   = (const int*)d_in[1];
    const float* ew   = (const float*)d_in[2];
    const int*   batch= (const int*)d_in[3];
    const float* Wl1  = (const float*)d_in[4];
    const float* bl1  = (const float*)d_in[5];
    const float* Wr1  = (const float*)d_in[6];
    const float* br1  = (const float*)d_in[7];
    const float* We1  = (const float*)d_in[8];
    const float* att1 = (const float*)d_in[9];
    const float* bias1= (const float*)d_in[10];
    const float* Wl2  = (const float*)d_in[11];
    const float* bl2  = (const float*)d_in[12];
    const float* Wr2  = (const float*)d_in[13];
    const float* br2  = (const float*)d_in[14];
    const float* We2  = (const float*)d_in[15];
    const float* att2 = (const float*)d_in[16];
    const float* bias2= (const float*)d_in[17];
    const float* fcW  = (const float*)d_in[18];
    const float* fcb  = (const float*)d_in[19];
    float* out = (float*)d_out;

    float* base = nullptr;
    cudaGetSymbolAddress((void**)&base, g_buf);
    float* XL   = base + OFF_XL;
    float* XR   = base + OFF_XR;
    float* Hb   = base + OFF_H;
    float* H2   = base + OFF_H2;
    int*   SSRC = (int*)(base + OFF_SSRC);
    float* SW   = base + OFF_SW;
    int*   OFFS = (int*)(base + OFF_OFFS);
    int*   CUR  = (int*)(base + OFF_CUR);
    float* LP   = base + OFF_LP;
    int*   BS   = (int*)(base + OFF_BS);
    float* PL   = base + OFF_PL;
    float* GC   = base + OFF_GC;

    cudaFuncSetAttribute(gemm_mma, cudaFuncAttributeMaxDynamicSharedMemorySize, G_SMEM);

    // ---- CSR build (dst-sorted edges) + self-loop attr + pool zero ----
    k_hist_zero<<<(NN + 255) / 256, 256>>>(CUR, LP, PL, GC);
    k_hist<<<(NE + 255) / 256, 256>>>(ei, ew, CUR, LP);
    k_scan1<<<SCAN_G, 256>>>(CUR, OFFS, BS);
    k_scan3<<<(NN + 255) / 256, 256>>>(OFFS, CUR, BS, LP);
    k_fill<<<(NE + 255) / 256, 256>>>(ei, ew, CUR, SSRC, SW);

    const int ggemm = (NN + 127) / 128;
    const int gattn = (NN * 32 + 255) / 256;

    // layer 1
    gemm_mma<<<ggemm, 512, G_SMEM>>>(x, Wl1, bl1, Wr1, br1, XL, XR, NN);
    k_attn<<<gattn, 256>>>(XL, XR, OFFS, SSRC, SW, LP, We1, att1, bias1, Hb);

    // layer 2
    gemm_mma<<<ggemm, 512, G_SMEM>>>(Hb, Wl2, bl2, Wr2, br2, XL, XR, NN);
    k_attn<<<gattn, 256>>>(XL, XR, OFFS, SSRC, SW, LP, We2, att2, bias2, H2);

    // mean pool per graph + fc
    k_pool_accum<<<(NN * 32 + 255) / 256, 256>>>(H2, batch, PL, GC);
    int wp = (out_size >= NG * OUTD + NG * HC) ? 1 : 0;
    k_tail<<<1, 512>>>(PL, GC, fcW, fcb, out, wp);
}